// round 1
// baseline (speedup 1.0000x reference)
#include <cuda_runtime.h>
#include <cuda_bf16.h>
#include <math.h>

// Problem constants
#define BATCH   4
#define SEQ     2048
#define DMODEL  1024
#define NHEAD   16
#define DHEAD   64
#define MROWS   (BATCH * SEQ)          // 8192
#define N_QKV   (3 * DMODEL)           // 3072
#define ATT_SCALE 0.125f               // 64^-0.5

// ---------------------------------------------------------------------------
// Device scratch (allocation-free rule: __device__ globals)
// ---------------------------------------------------------------------------
__device__ float g_qkv[(size_t)MROWS * N_QKV];                 // 96 MB
__device__ float g_q[(size_t)BATCH * NHEAD * SEQ * DHEAD];     // 32 MB
__device__ float g_k[(size_t)BATCH * NHEAD * SEQ * DHEAD];     // 32 MB
__device__ float g_v[(size_t)BATCH * NHEAD * SEQ * DHEAD];     // 32 MB
__device__ float g_ctx[(size_t)MROWS * DMODEL];                // 32 MB

// ---------------------------------------------------------------------------
// SGEMM (NT): C[m,n] = sum_k A[m,k] * B[n,k] + bias[n]
// A: [M,K] row-major, B: [N,K] row-major. M%128==0, N%128==0, K%16==0.
// 128x128 block tile, BK=16, 256 threads, 8x8 per-thread microtile.
// ---------------------------------------------------------------------------
#define GBM 128
#define GBN 128
#define GBK 16

__global__ __launch_bounds__(256)
void sgemm_nt_bias(const float* __restrict__ A, const float* __restrict__ B,
                   const float* __restrict__ bias, float* __restrict__ C,
                   int M, int N, int K)
{
    __shared__ float As[GBK][GBM];
    __shared__ float Bs[GBK][GBN];

    const int tid = threadIdx.x;
    const int bm = blockIdx.y * GBM;
    const int bn = blockIdx.x * GBN;
    const int ty = tid >> 4;        // 0..15
    const int tx = tid & 15;        // 0..15

    float acc[8][8];
#pragma unroll
    for (int i = 0; i < 8; i++)
#pragma unroll
        for (int j = 0; j < 8; j++) acc[i][j] = 0.f;

    for (int k0 = 0; k0 < K; k0 += GBK) {
        // Cooperative load: 512 float4 per operand tile, 2 per thread.
#pragma unroll
        for (int it = 0; it < 2; it++) {
            int slot = tid + 256 * it;       // 0..511
            int row  = slot >> 2;            // 0..127
            int kv   = (slot & 3) * 4;       // 0,4,8,12
            float4 a = *(const float4*)(A + (size_t)(bm + row) * K + k0 + kv);
            As[kv + 0][row] = a.x; As[kv + 1][row] = a.y;
            As[kv + 2][row] = a.z; As[kv + 3][row] = a.w;
            float4 b = *(const float4*)(B + (size_t)(bn + row) * K + k0 + kv);
            Bs[kv + 0][row] = b.x; Bs[kv + 1][row] = b.y;
            Bs[kv + 2][row] = b.z; Bs[kv + 3][row] = b.w;
        }
        __syncthreads();

#pragma unroll
        for (int kk = 0; kk < GBK; kk++) {
            float ar[8], br[8];
            float4 a0 = *(const float4*)&As[kk][ty * 8];
            float4 a1 = *(const float4*)&As[kk][ty * 8 + 4];
            ar[0] = a0.x; ar[1] = a0.y; ar[2] = a0.z; ar[3] = a0.w;
            ar[4] = a1.x; ar[5] = a1.y; ar[6] = a1.z; ar[7] = a1.w;
            float4 b0 = *(const float4*)&Bs[kk][tx * 8];
            float4 b1 = *(const float4*)&Bs[kk][tx * 8 + 4];
            br[0] = b0.x; br[1] = b0.y; br[2] = b0.z; br[3] = b0.w;
            br[4] = b1.x; br[5] = b1.y; br[6] = b1.z; br[7] = b1.w;
#pragma unroll
            for (int i = 0; i < 8; i++)
#pragma unroll
                for (int j = 0; j < 8; j++)
                    acc[i][j] = fmaf(ar[i], br[j], acc[i][j]);
        }
        __syncthreads();
    }

    // Epilogue with bias, float4 stores.
#pragma unroll
    for (int i = 0; i < 8; i++) {
        int row = bm + ty * 8 + i;
#pragma unroll
        for (int jv = 0; jv < 8; jv += 4) {
            int col = bn + tx * 8 + jv;
            float4 bb = *(const float4*)(bias + col);
            float4 r;
            r.x = acc[i][jv + 0] + bb.x;
            r.y = acc[i][jv + 1] + bb.y;
            r.z = acc[i][jv + 2] + bb.z;
            r.w = acc[i][jv + 3] + bb.w;
            *(float4*)(C + (size_t)row * N + col) = r;
        }
    }
}

// ---------------------------------------------------------------------------
// RoPE + split: qkv[M, 3072] -> q,k (roped), v in [B,H,S,Dh] layout.
// One thread per (b,h,s,i) with i in [0,32): handles pair (i, i+32) of q,k,v.
// ---------------------------------------------------------------------------
__global__ void rope_split_kernel(const float* __restrict__ qkv,
                                  const int* __restrict__ p,
                                  float* __restrict__ q,
                                  float* __restrict__ k,
                                  float* __restrict__ v)
{
    int t = blockIdx.x * blockDim.x + threadIdx.x;
    const int total = BATCH * NHEAD * SEQ * 32;
    if (t >= total) return;
    int i = t & 31;
    int s = (t >> 5) & (SEQ - 1);
    int h = (t >> 16) & (NHEAD - 1);
    int b = t >> 20;

    int m = b * SEQ + s;
    const float* row = qkv + (size_t)m * N_QKV;
    int col = h * DHEAD + i;
    float qa = row[col],            qb = row[col + 32];
    float ka = row[DMODEL + col],   kb = row[DMODEL + col + 32];
    float va = row[2*DMODEL + col], vb = row[2*DMODEL + col + 32];

    float pos = (float)p[m];
    // freq = 10000^(-i/32), computed in double to match fp32 reference to ~1 ulp
    float f = (float)exp2(-(double)i * (13.287712379549449 / 32.0)); // log2(10000)
    float ang = pos * f;
    float sn, cs;
    sincosf(ang, &sn, &cs);

    size_t o = ((size_t)(b * NHEAD + h) * SEQ + s) * DHEAD + i;
    q[o]      = qa * cs + qb * sn;
    q[o + 32] = qb * cs - qa * sn;
    k[o]      = ka * cs + kb * sn;
    k[o + 32] = kb * cs - ka * sn;
    v[o]      = va;
    v[o + 32] = vb;
}

// ---------------------------------------------------------------------------
// Flash attention (fp32). One block per (b,h, 128-row q tile); 128 threads,
// one q row per thread. q, o, s live in registers (loops fully unrolled).
// K/V tiles (32 x 64) staged in smem; all smem reads in the math loops are
// warp-broadcast (conflict-free). Output staged through smem for coalesced
// writes into ctx[B,S,D] ( = [b, s, h*64+d]).
// ---------------------------------------------------------------------------
#define AT_TQ 128
#define AT_TK 32

__global__ __launch_bounds__(128)
void flash_attn_kernel(const float* __restrict__ Q, const float* __restrict__ K,
                       const float* __restrict__ V, float* __restrict__ ctx)
{
    // 32 KB: K tile (8KB) + V tile (8KB) during mainloop; reused as 32KB
    // output staging tile in the epilogue.
    __shared__ float4 smem[2048];
    float4* Ks4 = smem;          // [AT_TK*16]
    float4* Vs4 = smem + 512;    // [AT_TK*16]

    const int i = threadIdx.x;              // q row within tile
    const int bh = blockIdx.y;
    const int b = bh >> 4, h = bh & 15;
    const int s0 = blockIdx.x * AT_TQ;

    const float4* qp = (const float4*)(Q + ((size_t)bh * SEQ + s0 + i) * DHEAD);
    float4 q4[16];
#pragma unroll
    for (int d = 0; d < 16; d++) q4[d] = qp[d];

    float4 o4[16];
#pragma unroll
    for (int d = 0; d < 16; d++) o4[d] = make_float4(0.f, 0.f, 0.f, 0.f);

    float mrun = -1e30f, lrun = 0.f;

    const float4* kbase = (const float4*)(K + (size_t)bh * SEQ * DHEAD);
    const float4* vbase = (const float4*)(V + (size_t)bh * SEQ * DHEAD);

    for (int kt = 0; kt < SEQ / AT_TK; kt++) {
        __syncthreads();
        // K/V tiles are contiguous [32 rows x 64 floats] = 512 float4 each.
#pragma unroll
        for (int it = 0; it < 4; it++) {
            int slot = i + 128 * it;
            Ks4[slot] = kbase[kt * 512 + slot];
            Vs4[slot] = vbase[kt * 512 + slot];
        }
        __syncthreads();

        float s[AT_TK];
        float mt = mrun;
#pragma unroll
        for (int j = 0; j < AT_TK; j++) {
            float acc = 0.f;
#pragma unroll
            for (int d = 0; d < 16; d++) {
                float4 kv = Ks4[j * 16 + d];   // broadcast
                acc = fmaf(q4[d].x, kv.x, acc);
                acc = fmaf(q4[d].y, kv.y, acc);
                acc = fmaf(q4[d].z, kv.z, acc);
                acc = fmaf(q4[d].w, kv.w, acc);
            }
            s[j] = acc * ATT_SCALE;
            mt = fmaxf(mt, s[j]);
        }

        float corr = __expf(mrun - mt);
        mrun = mt;
        float sum = 0.f;
#pragma unroll
        for (int j = 0; j < AT_TK; j++) {
            s[j] = __expf(s[j] - mt);
            sum += s[j];
        }
        lrun = lrun * corr + sum;
#pragma unroll
        for (int d = 0; d < 16; d++) {
            o4[d].x *= corr; o4[d].y *= corr; o4[d].z *= corr; o4[d].w *= corr;
        }
#pragma unroll
        for (int j = 0; j < AT_TK; j++) {
            float pj = s[j];
#pragma unroll
            for (int d = 0; d < 16; d++) {
                float4 vv = Vs4[j * 16 + d];   // broadcast
                o4[d].x = fmaf(pj, vv.x, o4[d].x);
                o4[d].y = fmaf(pj, vv.y, o4[d].y);
                o4[d].z = fmaf(pj, vv.z, o4[d].z);
                o4[d].w = fmaf(pj, vv.w, o4[d].w);
            }
        }
    }

    float inv = 1.f / lrun;
#pragma unroll
    for (int d = 0; d < 16; d++) {
        o4[d].x *= inv; o4[d].y *= inv; o4[d].z *= inv; o4[d].w *= inv;
    }

    // Stage output tile [128 rows x 64 floats] in smem, then coalesced write
    // into ctx[b][s][h*64 + d].
    __syncthreads();
#pragma unroll
    for (int d = 0; d < 16; d++) smem[i * 16 + d] = o4[d];
    __syncthreads();

    float4* ctx4 = (float4*)ctx;
#pragma unroll
    for (int it = 0; it < 16; it++) {
        int slot = i + 128 * it;       // 0..2047
        int row  = slot >> 4;          // 0..127
        int dv   = slot & 15;          // 0..15
        size_t gidx = ((size_t)(b * SEQ + s0 + row)) * (DMODEL / 4) + h * 16 + dv;
        ctx4[gidx] = smem[slot];
    }
}

// ---------------------------------------------------------------------------
// Launch
// ---------------------------------------------------------------------------
extern "C" void kernel_launch(void* const* d_in, const int* in_sizes, int n_in,
                              void* d_out, int out_size)
{
    (void)in_sizes; (void)n_in; (void)out_size;
    const float* x      = (const float*)d_in[0];   // [4,2048,1024]
    const int*   p      = (const int*)  d_in[1];   // [4,2048]
    const float* Wqkv_w = (const float*)d_in[2];   // [3072,1024]
    const float* Wqkv_b = (const float*)d_in[3];   // [3072]
    const float* Wo_w   = (const float*)d_in[4];   // [1024,1024]
    const float* Wo_b   = (const float*)d_in[5];   // [1024]
    float* out = (float*)d_out;                    // [4,2048,1024]

    float *qkv, *q, *k, *v, *ctx;
    cudaGetSymbolAddress((void**)&qkv, g_qkv);
    cudaGetSymbolAddress((void**)&q,   g_q);
    cudaGetSymbolAddress((void**)&k,   g_k);
    cudaGetSymbolAddress((void**)&v,   g_v);
    cudaGetSymbolAddress((void**)&ctx, g_ctx);

    // 1) QKV projection
    {
        dim3 grid(N_QKV / GBN, MROWS / GBM);
        sgemm_nt_bias<<<grid, 256>>>(x, Wqkv_w, Wqkv_b, qkv, MROWS, N_QKV, DMODEL);
    }
    // 2) RoPE + split into [B,H,S,Dh]
    {
        int total = BATCH * NHEAD * SEQ * 32;
        rope_split_kernel<<<(total + 255) / 256, 256>>>(qkv, p, q, k, v);
    }
    // 3) Flash attention -> ctx in [B,S,D]
    {
        dim3 grid(SEQ / AT_TQ, BATCH * NHEAD);
        flash_attn_kernel<<<grid, 128>>>(q, k, v, ctx);
    }
    // 4) Output projection
    {
        dim3 grid(DMODEL / GBN, MROWS / GBM);
        sgemm_nt_bias<<<grid, 256>>>(ctx, Wo_w, Wo_b, out, MROWS, DMODEL, DMODEL);
    }
}

// round 3
// speedup vs baseline: 1.4633x; 1.4633x over previous
#include <cuda_runtime.h>
#include <cuda_bf16.h>
#include <math.h>

// Problem constants
#define BATCH   4
#define SEQ     2048
#define DMODEL  1024
#define NHEAD   16
#define DHEAD   64
#define MROWS   (BATCH * SEQ)          // 8192
#define N_QKV   (3 * DMODEL)           // 3072
#define ATT_SCALE 0.125f               // 64^-0.5

typedef unsigned long long ull;

// ---------------------------------------------------------------------------
// Device scratch (allocation-free rule: __device__ globals)
// ---------------------------------------------------------------------------
__device__ float g_qkv[(size_t)MROWS * N_QKV];                 // 96 MB
__device__ float g_q[(size_t)BATCH * NHEAD * SEQ * DHEAD];     // 32 MB
__device__ float g_k[(size_t)BATCH * NHEAD * SEQ * DHEAD];     // 32 MB
__device__ float g_v[(size_t)BATCH * NHEAD * SEQ * DHEAD];     // 32 MB
__device__ float g_ctx[(size_t)MROWS * DMODEL];                // 32 MB

// ---------------------------------------------------------------------------
// f32x2 packed-math helpers (FFMA2 — only reachable via PTX)
// ---------------------------------------------------------------------------
__device__ __forceinline__ ull ffma2(ull a, ull b, ull c) {
    ull d;
    asm("fma.rn.f32x2 %0, %1, %2, %3;" : "=l"(d) : "l"(a), "l"(b), "l"(c));
    return d;
}
__device__ __forceinline__ ull fmul2(ull a, ull b) {
    ull d;
    asm("mul.rn.f32x2 %0, %1, %2;" : "=l"(d) : "l"(a), "l"(b));
    return d;
}
__device__ __forceinline__ ull fadd2(ull a, ull b) {
    ull d;
    asm("add.rn.f32x2 %0, %1, %2;" : "=l"(d) : "l"(a), "l"(b));
    return d;
}
__device__ __forceinline__ ull pack2(float lo, float hi) {
    ull d;
    asm("mov.b64 %0, {%1, %2};" : "=l"(d) : "f"(lo), "f"(hi));
    return d;
}
__device__ __forceinline__ void unpack2(ull v, float& lo, float& hi) {
    asm("mov.b64 {%0, %1}, %2;" : "=f"(lo), "=f"(hi) : "l"(v));
}
__device__ __forceinline__ unsigned f2tf32(float f) {
    unsigned u;
    asm("cvt.rna.tf32.f32 %0, %1;" : "=r"(u) : "f"(f));
    return u;
}

// ---------------------------------------------------------------------------
// TF32 tensor-core GEMM (NT): C[m,n] = sum_k A[m,k]*B[n,k] + bias[n]
// A:[M,K] row-major, B:[N,K] row-major. M%128==0, N%128==0, K%32==0.
// Block tile 128x128, BK=32, 256 threads (8 warps), warp tile 32x64
// (2 x m16 tiles, 8 x n8 tiles), mma.sync.m16n8k8 tf32.
// ---------------------------------------------------------------------------
#define TBM 128
#define TBN 128
#define TBK 32
#define SMP 36   // padded row stride (floats) for conflict-free fragment LDS

__global__ __launch_bounds__(256, 1)
void tf32gemm_nt_bias(const float* __restrict__ A, const float* __restrict__ B,
                      const float* __restrict__ bias, float* __restrict__ C,
                      int M, int N, int K)
{
    __shared__ unsigned As[TBM * SMP];
    __shared__ unsigned Bs[TBN * SMP];

    const int tid  = threadIdx.x;
    const int lane = tid & 31;
    const int wid  = tid >> 5;          // 0..7
    const int wm   = wid >> 1;          // 0..3 -> 32 rows each
    const int wn   = wid & 1;           // 0..1 -> 64 cols each
    const int g    = lane >> 2;         // 0..7
    const int t    = lane & 3;          // 0..3

    const int bm = blockIdx.y * TBM;
    const int bn = blockIdx.x * TBN;

    float acc[2][8][4];
#pragma unroll
    for (int mt = 0; mt < 2; mt++)
#pragma unroll
        for (int nt = 0; nt < 8; nt++)
#pragma unroll
            for (int r = 0; r < 4; r++) acc[mt][nt][r] = 0.f;

    for (int k0 = 0; k0 < K; k0 += TBK) {
        // Cooperative load + tf32 convert: 1024 float4 per operand, 4/thread.
#pragma unroll
        for (int it = 0; it < 4; it++) {
            int slot = tid + 256 * it;      // 0..1023
            int row  = slot >> 3;           // 0..127
            int kv   = (slot & 7) * 4;      // 0..28
            float4 a = *(const float4*)(A + (size_t)(bm + row) * K + k0 + kv);
            uint4 ua = make_uint4(f2tf32(a.x), f2tf32(a.y), f2tf32(a.z), f2tf32(a.w));
            *(uint4*)&As[row * SMP + kv] = ua;
            float4 b = *(const float4*)(B + (size_t)(bn + row) * K + k0 + kv);
            uint4 ub = make_uint4(f2tf32(b.x), f2tf32(b.y), f2tf32(b.z), f2tf32(b.w));
            *(uint4*)&Bs[row * SMP + kv] = ub;
        }
        __syncthreads();

#pragma unroll
        for (int kk = 0; kk < TBK; kk += 8) {
            unsigned af[2][4], bf[8][2];
#pragma unroll
            for (int mt = 0; mt < 2; mt++) {
                int m0 = wm * 32 + mt * 16;
                af[mt][0] = As[(m0 + g)     * SMP + kk + t];
                af[mt][1] = As[(m0 + g + 8) * SMP + kk + t];
                af[mt][2] = As[(m0 + g)     * SMP + kk + t + 4];
                af[mt][3] = As[(m0 + g + 8) * SMP + kk + t + 4];
            }
#pragma unroll
            for (int nt = 0; nt < 8; nt++) {
                int n0 = wn * 64 + nt * 8;
                bf[nt][0] = Bs[(n0 + g) * SMP + kk + t];
                bf[nt][1] = Bs[(n0 + g) * SMP + kk + t + 4];
            }
#pragma unroll
            for (int mt = 0; mt < 2; mt++)
#pragma unroll
                for (int nt = 0; nt < 8; nt++) {
                    asm("mma.sync.aligned.m16n8k8.row.col.f32.tf32.tf32.f32 "
                        "{%0,%1,%2,%3}, {%4,%5,%6,%7}, {%8,%9}, {%0,%1,%2,%3};"
                        : "+f"(acc[mt][nt][0]), "+f"(acc[mt][nt][1]),
                          "+f"(acc[mt][nt][2]), "+f"(acc[mt][nt][3])
                        : "r"(af[mt][0]), "r"(af[mt][1]), "r"(af[mt][2]), "r"(af[mt][3]),
                          "r"(bf[nt][0]), "r"(bf[nt][1]));
                }
        }
        __syncthreads();
    }

    // Epilogue: bias + float2 stores.
#pragma unroll
    for (int mt = 0; mt < 2; mt++) {
        int row0 = bm + wm * 32 + mt * 16 + g;
#pragma unroll
        for (int nt = 0; nt < 8; nt++) {
            int col = bn + wn * 64 + nt * 8 + 2 * t;
            float bx = bias[col], by = bias[col + 1];
            float2 r0 = make_float2(acc[mt][nt][0] + bx, acc[mt][nt][1] + by);
            float2 r1 = make_float2(acc[mt][nt][2] + bx, acc[mt][nt][3] + by);
            *(float2*)(C + (size_t)row0 * N + col)       = r0;
            *(float2*)(C + (size_t)(row0 + 8) * N + col) = r1;
        }
    }
}

// ---------------------------------------------------------------------------
// RoPE + split: qkv[M, 3072] -> q,k (roped), v in [B,H,S,Dh] layout.
// ---------------------------------------------------------------------------
__global__ void rope_split_kernel(const float* __restrict__ qkv,
                                  const int* __restrict__ p,
                                  float* __restrict__ q,
                                  float* __restrict__ k,
                                  float* __restrict__ v)
{
    int t = blockIdx.x * blockDim.x + threadIdx.x;
    const int total = BATCH * NHEAD * SEQ * 32;
    if (t >= total) return;
    int i = t & 31;
    int s = (t >> 5) & (SEQ - 1);
    int h = (t >> 16) & (NHEAD - 1);
    int b = t >> 20;

    int m = b * SEQ + s;
    const float* row = qkv + (size_t)m * N_QKV;
    int col = h * DHEAD + i;
    float qa = row[col],            qb = row[col + 32];
    float ka = row[DMODEL + col],   kb = row[DMODEL + col + 32];
    float va = row[2*DMODEL + col], vb = row[2*DMODEL + col + 32];

    float pos = (float)p[m];
    float f = (float)exp2(-(double)i * (13.287712379549449 / 32.0)); // log2(10000)
    float ang = pos * f;
    float sn, cs;
    sincosf(ang, &sn, &cs);

    size_t o = ((size_t)(b * NHEAD + h) * SEQ + s) * DHEAD + i;
    q[o]      = qa * cs + qb * sn;
    q[o + 32] = qb * cs - qa * sn;
    k[o]      = ka * cs + kb * sn;
    k[o + 32] = kb * cs - ka * sn;
    v[o]      = va;
    v[o + 32] = vb;
}

// ---------------------------------------------------------------------------
// Flash attention with packed f32x2 math (FFMA2: 2x fp32 rate).
// One block per (b,h, 128-row q tile); 128 threads, one q row per thread.
// q/o rows in packed registers; K/V tiles (32x64) staged in smem.
// QK dot uses two accumulator chains to hide FFMA2 latency.
// ---------------------------------------------------------------------------
#define AT_TQ 128
#define AT_TK 32

__global__ __launch_bounds__(128)
void flash_attn_kernel(const float* __restrict__ Q, const float* __restrict__ K,
                       const float* __restrict__ V, float* __restrict__ ctx)
{
    __shared__ float4 smem[2048];      // 32 KB
    const ull* Ks2 = (const ull*)smem;         // [32 rows][32 f32x2]
    const ull* Vs2 = (const ull*)(smem + 512);

    const int i = threadIdx.x;
    const int bh = blockIdx.y;
    const int b = bh >> 4, h = bh & 15;
    const int s0 = blockIdx.x * AT_TQ;

    const ull* qp = (const ull*)(Q + ((size_t)bh * SEQ + s0 + i) * DHEAD);
    ull q2[32];
#pragma unroll
    for (int d = 0; d < 32; d++) q2[d] = qp[d];

    ull o2[32];
#pragma unroll
    for (int d = 0; d < 32; d++) o2[d] = 0ull;   // (0.f, 0.f)

    float mrun = -1e30f, lrun = 0.f;

    const float4* kbase = (const float4*)(K + (size_t)bh * SEQ * DHEAD);
    const float4* vbase = (const float4*)(V + (size_t)bh * SEQ * DHEAD);

    for (int kt = 0; kt < SEQ / AT_TK; kt++) {
        __syncthreads();
#pragma unroll
        for (int it = 0; it < 4; it++) {
            int slot = i + 128 * it;
            ((float4*)smem)[slot]         = kbase[kt * 512 + slot];
            ((float4*)(smem + 512))[slot] = vbase[kt * 512 + slot];
        }
        __syncthreads();

        float s[AT_TK];
        float mt = mrun;
#pragma unroll
        for (int j = 0; j < AT_TK; j++) {
            ull acca = 0ull, accb = 0ull;   // two chains to hide latency
#pragma unroll
            for (int d = 0; d < 32; d += 2) {
                acca = ffma2(q2[d],     Ks2[j * 32 + d],     acca);
                accb = ffma2(q2[d + 1], Ks2[j * 32 + d + 1], accb);
            }
            ull acc = fadd2(acca, accb);
            float lo, hi; unpack2(acc, lo, hi);
            s[j] = (lo + hi) * ATT_SCALE;
            mt = fmaxf(mt, s[j]);
        }

        float corr = __expf(mrun - mt);
        mrun = mt;
        float sum = 0.f;
#pragma unroll
        for (int j = 0; j < AT_TK; j++) {
            s[j] = __expf(s[j] - mt);
            sum += s[j];
        }
        lrun = lrun * corr + sum;

        ull corr2 = pack2(corr, corr);
#pragma unroll
        for (int d = 0; d < 32; d++) o2[d] = fmul2(o2[d], corr2);

#pragma unroll
        for (int j = 0; j < AT_TK; j++) {
            ull p2 = pack2(s[j], s[j]);
#pragma unroll
            for (int d = 0; d < 32; d++)
                o2[d] = ffma2(p2, Vs2[j * 32 + d], o2[d]);
        }
    }

    float inv = 1.f / lrun;
    ull inv2 = pack2(inv, inv);
#pragma unroll
    for (int d = 0; d < 32; d++) o2[d] = fmul2(o2[d], inv2);

    // Stage output tile [128 x 64] in smem, coalesced write into ctx[B,S,D].
    __syncthreads();
#pragma unroll
    for (int d = 0; d < 32; d++) ((ull*)smem)[i * 32 + d] = o2[d];
    __syncthreads();

    float4* ctx4 = (float4*)ctx;
#pragma unroll
    for (int it = 0; it < 16; it++) {
        int slot = i + 128 * it;       // 0..2047
        int row  = slot >> 4;          // 0..127
        int dv   = slot & 15;          // 0..15
        size_t gidx = ((size_t)(b * SEQ + s0 + row)) * (DMODEL / 4) + h * 16 + dv;
        ctx4[gidx] = smem[slot];
    }
}

// ---------------------------------------------------------------------------
// Launch
// ---------------------------------------------------------------------------
extern "C" void kernel_launch(void* const* d_in, const int* in_sizes, int n_in,
                              void* d_out, int out_size)
{
    (void)in_sizes; (void)n_in; (void)out_size;
    const float* x      = (const float*)d_in[0];   // [4,2048,1024]
    const int*   p      = (const int*)  d_in[1];   // [4,2048]
    const float* Wqkv_w = (const float*)d_in[2];   // [3072,1024]
    const float* Wqkv_b = (const float*)d_in[3];   // [3072]
    const float* Wo_w   = (const float*)d_in[4];   // [1024,1024]
    const float* Wo_b   = (const float*)d_in[5];   // [1024]
    float* out = (float*)d_out;                    // [4,2048,1024]

    float *qkv, *q, *k, *v, *ctx;
    cudaGetSymbolAddress((void**)&qkv, g_qkv);
    cudaGetSymbolAddress((void**)&q,   g_q);
    cudaGetSymbolAddress((void**)&k,   g_k);
    cudaGetSymbolAddress((void**)&v,   g_v);
    cudaGetSymbolAddress((void**)&ctx, g_ctx);

    // 1) QKV projection (tf32 tensor cores)
    {
        dim3 grid(N_QKV / TBN, MROWS / TBM);
        tf32gemm_nt_bias<<<grid, 256>>>(x, Wqkv_w, Wqkv_b, qkv, MROWS, N_QKV, DMODEL);
    }
    // 2) RoPE + split into [B,H,S,Dh]
    {
        int total = BATCH * NHEAD * SEQ * 32;
        rope_split_kernel<<<(total + 255) / 256, 256>>>(qkv, p, q, k, v);
    }
    // 3) Flash attention -> ctx in [B,S,D]
    {
        dim3 grid(SEQ / AT_TQ, BATCH * NHEAD);
        flash_attn_kernel<<<grid, 128>>>(q, k, v, ctx);
    }
    // 4) Output projection (tf32 tensor cores)
    {
        dim3 grid(DMODEL / TBN, MROWS / TBM);
        tf32gemm_nt_bias<<<grid, 256>>>(ctx, Wo_w, Wo_b, out, MROWS, DMODEL, DMODEL);
    }
}

// round 5
// speedup vs baseline: 2.9063x; 1.9860x over previous
#include <cuda_runtime.h>
#include <cuda_bf16.h>
#include <math.h>

// Problem constants
#define BATCH   4
#define SEQ     2048
#define DMODEL  1024
#define NHEAD   16
#define DHEAD   64
#define MROWS   (BATCH * SEQ)          // 8192
#define N_QKV   (3 * DMODEL)           // 3072
#define ATT_SCALE 0.125f               // 64^-0.5 (exact power of two)

typedef unsigned long long ull;

// ---------------------------------------------------------------------------
// Device scratch (allocation-free rule: __device__ globals)
// ---------------------------------------------------------------------------
__device__ float g_qkv[(size_t)MROWS * N_QKV];                 // 96 MB
__device__ float g_q[(size_t)BATCH * NHEAD * SEQ * DHEAD];     // 32 MB
__device__ float g_k[(size_t)BATCH * NHEAD * SEQ * DHEAD];     // 32 MB
__device__ float g_v[(size_t)BATCH * NHEAD * SEQ * DHEAD];     // 32 MB
__device__ float g_ctx[(size_t)MROWS * DMODEL];                // 32 MB

__device__ __forceinline__ unsigned f2tf32(float f) {
    unsigned u;
    asm("cvt.rna.tf32.f32 %0, %1;" : "=r"(u) : "f"(f));
    return u;
}

__device__ __forceinline__ void mma_tf32(float* c, const unsigned* a,
                                         unsigned b0, unsigned b1) {
    asm("mma.sync.aligned.m16n8k8.row.col.f32.tf32.tf32.f32 "
        "{%0,%1,%2,%3}, {%4,%5,%6,%7}, {%8,%9}, {%0,%1,%2,%3};"
        : "+f"(c[0]), "+f"(c[1]), "+f"(c[2]), "+f"(c[3])
        : "r"(a[0]), "r"(a[1]), "r"(a[2]), "r"(a[3]), "r"(b0), "r"(b1));
}

// ---------------------------------------------------------------------------
// TF32 tensor-core GEMM (NT): C[m,n] = sum_k A[m,k]*B[n,k] + bias[n]
// Block tile 128x128, BK=32, 256 threads (8 warps), warp tile 32x64.
// ---------------------------------------------------------------------------
#define TBM 128
#define TBN 128
#define TBK 32
#define SMP 36   // padded row stride (floats)

__global__ __launch_bounds__(256, 1)
void tf32gemm_nt_bias(const float* __restrict__ A, const float* __restrict__ B,
                      const float* __restrict__ bias, float* __restrict__ C,
                      int M, int N, int K)
{
    __shared__ unsigned As[TBM * SMP];
    __shared__ unsigned Bs[TBN * SMP];

    const int tid  = threadIdx.x;
    const int lane = tid & 31;
    const int wid  = tid >> 5;
    const int wm   = wid >> 1;
    const int wn   = wid & 1;
    const int g    = lane >> 2;
    const int t    = lane & 3;

    const int bm = blockIdx.y * TBM;
    const int bn = blockIdx.x * TBN;

    float acc[2][8][4];
#pragma unroll
    for (int mt = 0; mt < 2; mt++)
#pragma unroll
        for (int nt = 0; nt < 8; nt++)
#pragma unroll
            for (int r = 0; r < 4; r++) acc[mt][nt][r] = 0.f;

    for (int k0 = 0; k0 < K; k0 += TBK) {
#pragma unroll
        for (int it = 0; it < 4; it++) {
            int slot = tid + 256 * it;
            int row  = slot >> 3;
            int kv   = (slot & 7) * 4;
            float4 a = *(const float4*)(A + (size_t)(bm + row) * K + k0 + kv);
            uint4 ua = make_uint4(f2tf32(a.x), f2tf32(a.y), f2tf32(a.z), f2tf32(a.w));
            *(uint4*)&As[row * SMP + kv] = ua;
            float4 b = *(const float4*)(B + (size_t)(bn + row) * K + k0 + kv);
            uint4 ub = make_uint4(f2tf32(b.x), f2tf32(b.y), f2tf32(b.z), f2tf32(b.w));
            *(uint4*)&Bs[row * SMP + kv] = ub;
        }
        __syncthreads();

#pragma unroll
        for (int kk = 0; kk < TBK; kk += 8) {
            unsigned af[2][4], bf[8][2];
#pragma unroll
            for (int mt = 0; mt < 2; mt++) {
                int m0 = wm * 32 + mt * 16;
                af[mt][0] = As[(m0 + g)     * SMP + kk + t];
                af[mt][1] = As[(m0 + g + 8) * SMP + kk + t];
                af[mt][2] = As[(m0 + g)     * SMP + kk + t + 4];
                af[mt][3] = As[(m0 + g + 8) * SMP + kk + t + 4];
            }
#pragma unroll
            for (int nt = 0; nt < 8; nt++) {
                int n0 = wn * 64 + nt * 8;
                bf[nt][0] = Bs[(n0 + g) * SMP + kk + t];
                bf[nt][1] = Bs[(n0 + g) * SMP + kk + t + 4];
            }
#pragma unroll
            for (int mt = 0; mt < 2; mt++)
#pragma unroll
                for (int nt = 0; nt < 8; nt++)
                    mma_tf32(acc[mt][nt], af[mt], bf[nt][0], bf[nt][1]);
        }
        __syncthreads();
    }

#pragma unroll
    for (int mt = 0; mt < 2; mt++) {
        int row0 = bm + wm * 32 + mt * 16 + g;
#pragma unroll
        for (int nt = 0; nt < 8; nt++) {
            int col = bn + wn * 64 + nt * 8 + 2 * t;
            float bx = bias[col], by = bias[col + 1];
            float2 r0 = make_float2(acc[mt][nt][0] + bx, acc[mt][nt][1] + by);
            float2 r1 = make_float2(acc[mt][nt][2] + bx, acc[mt][nt][3] + by);
            *(float2*)(C + (size_t)row0 * N + col)       = r0;
            *(float2*)(C + (size_t)(row0 + 8) * N + col) = r1;
        }
    }
}

// ---------------------------------------------------------------------------
// RoPE + split: qkv[M, 3072] -> q,k (roped), v in [B,H,S,Dh] layout.
// ---------------------------------------------------------------------------
__global__ void rope_split_kernel(const float* __restrict__ qkv,
                                  const int* __restrict__ p,
                                  float* __restrict__ q,
                                  float* __restrict__ k,
                                  float* __restrict__ v)
{
    int t = blockIdx.x * blockDim.x + threadIdx.x;
    const int total = BATCH * NHEAD * SEQ * 32;
    if (t >= total) return;
    int i = t & 31;
    int s = (t >> 5) & (SEQ - 1);
    int h = (t >> 16) & (NHEAD - 1);
    int b = t >> 20;

    int m = b * SEQ + s;
    const float* row = qkv + (size_t)m * N_QKV;
    int col = h * DHEAD + i;
    float qa = row[col],            qb = row[col + 32];
    float ka = row[DMODEL + col],   kb = row[DMODEL + col + 32];
    float va = row[2*DMODEL + col], vb = row[2*DMODEL + col + 32];

    float pos = (float)p[m];
    float f = (float)exp2(-(double)i * (13.287712379549449 / 32.0)); // log2(10000)
    float ang = pos * f;
    float sn, cs;
    sincosf(ang, &sn, &cs);

    size_t o = ((size_t)(b * NHEAD + h) * SEQ + s) * DHEAD + i;
    q[o]      = qa * cs + qb * sn;
    q[o + 32] = qb * cs - qa * sn;
    k[o]      = ka * cs + kb * sn;
    k[o + 32] = kb * cs - ka * sn;
    v[o]      = va;
    v[o + 32] = vb;
}

// ---------------------------------------------------------------------------
// Tensor-core flash attention (tf32 mma.m16n8k8).
// Block: 256 threads / 8 warps. TQ=128 q rows (warp w owns rows w*16..w*16+15),
// TK=64 k rows per mainloop tile. Q pre-scaled by ATT_SCALE, tf32.
// K smem stride 68, V smem stride 72 (both give conflict-free fragment LDS).
// P->A-operand layout fix via 8 shfls per k-step (no smem round trip).
// ---------------------------------------------------------------------------
#define FTQ 128
#define FTK 64
#define KSTR 68
#define VSTR 72

__global__ __launch_bounds__(256, 1)
void flash_attn_tc_kernel(const float* __restrict__ Q, const float* __restrict__ K,
                          const float* __restrict__ V, float* __restrict__ ctx)
{
    __shared__ __align__(16) unsigned sm[FTK * KSTR + FTK * VSTR]; // 35840 B
    unsigned* Ks = sm;
    unsigned* Vs = sm + FTK * KSTR;

    const int tid  = threadIdx.x;
    const int lane = tid & 31;
    const int wid  = tid >> 5;         // 0..7 -> q-row tile
    const int g    = lane >> 2;        // 0..7
    const int t    = lane & 3;         // 0..3

    const int bh = blockIdx.y;
    const int b = bh >> 4, h = bh & 15;
    const int s0 = blockIdx.x * FTQ;

    const float* qbase = Q + (size_t)bh * SEQ * DHEAD;
    const float* kbase = K + (size_t)bh * SEQ * DHEAD;
    const float* vbase = V + (size_t)bh * SEQ * DHEAD;

    // --- Stage Q tile [128][64] into smem (scaled, tf32), then build A frags.
#pragma unroll
    for (int it = 0; it < 8; it++) {
        int slot = tid + 256 * it;       // 0..2047
        int row  = slot >> 4;
        int c4   = (slot & 15) * 4;
        float4 qv = *(const float4*)(qbase + (size_t)(s0 + row) * DHEAD + c4);
        uint4 uq = make_uint4(f2tf32(qv.x * ATT_SCALE), f2tf32(qv.y * ATT_SCALE),
                              f2tf32(qv.z * ATT_SCALE), f2tf32(qv.w * ATT_SCALE));
        *(uint4*)&sm[row * KSTR + c4] = uq;
    }
    __syncthreads();

    unsigned qf[8][4];
    {
        int r0 = wid * 16 + g;
#pragma unroll
        for (int kk = 0; kk < 8; kk++) {
            qf[kk][0] = sm[(r0)     * KSTR + kk * 8 + t];
            qf[kk][1] = sm[(r0 + 8) * KSTR + kk * 8 + t];
            qf[kk][2] = sm[(r0)     * KSTR + kk * 8 + t + 4];
            qf[kk][3] = sm[(r0 + 8) * KSTR + kk * 8 + t + 4];
        }
    }

    float oacc[8][4];
#pragma unroll
    for (int nt = 0; nt < 8; nt++)
#pragma unroll
        for (int r = 0; r < 4; r++) oacc[nt][r] = 0.f;

    float m0 = -1e30f, m1 = -1e30f, l0 = 0.f, l1 = 0.f;

    const unsigned FULL = 0xffffffffu;
    const int srcA = (lane & ~3) | (t >> 1);
    const int srcB = srcA + 2;

    for (int kt = 0; kt < SEQ / FTK; kt++) {
        __syncthreads();
        // Load K/V tiles [64][64] -> smem tf32. 1024 float4 each, 4/thread.
#pragma unroll
        for (int it = 0; it < 4; it++) {
            int slot = tid + 256 * it;     // 0..1023
            int row  = slot >> 4;
            int c4   = (slot & 15) * 4;
            float4 kv = *(const float4*)(kbase + (size_t)(kt * FTK + row) * DHEAD + c4);
            *(uint4*)&Ks[row * KSTR + c4] =
                make_uint4(f2tf32(kv.x), f2tf32(kv.y), f2tf32(kv.z), f2tf32(kv.w));
            float4 vv = *(const float4*)(vbase + (size_t)(kt * FTK + row) * DHEAD + c4);
            *(uint4*)&Vs[row * VSTR + c4] =
                make_uint4(f2tf32(vv.x), f2tf32(vv.y), f2tf32(vv.z), f2tf32(vv.w));
        }
        __syncthreads();

        // ---- S = Q K^T  (scaled): 8 ntiles (k-rows) x 8 ksteps (dh)
        float s[8][4];
#pragma unroll
        for (int nt = 0; nt < 8; nt++)
#pragma unroll
            for (int r = 0; r < 4; r++) s[nt][r] = 0.f;

#pragma unroll
        for (int kk = 0; kk < 8; kk++) {
#pragma unroll
            for (int nt = 0; nt < 8; nt++) {
                unsigned b0 = Ks[(nt * 8 + g) * KSTR + kk * 8 + t];
                unsigned b1 = Ks[(nt * 8 + g) * KSTR + kk * 8 + t + 4];
                mma_tf32(s[nt], qf[kk], b0, b1);
            }
        }

        // ---- online softmax on fragments
        float tm0 = -1e30f, tm1 = -1e30f;
#pragma unroll
        for (int nt = 0; nt < 8; nt++) {
            tm0 = fmaxf(tm0, fmaxf(s[nt][0], s[nt][1]));
            tm1 = fmaxf(tm1, fmaxf(s[nt][2], s[nt][3]));
        }
        tm0 = fmaxf(tm0, __shfl_xor_sync(FULL, tm0, 1));
        tm0 = fmaxf(tm0, __shfl_xor_sync(FULL, tm0, 2));
        tm1 = fmaxf(tm1, __shfl_xor_sync(FULL, tm1, 1));
        tm1 = fmaxf(tm1, __shfl_xor_sync(FULL, tm1, 2));

        float mn0 = fmaxf(m0, tm0), mn1 = fmaxf(m1, tm1);
        float corr0 = __expf(m0 - mn0), corr1 = __expf(m1 - mn1);
        m0 = mn0; m1 = mn1;

        float sum0 = 0.f, sum1 = 0.f;
#pragma unroll
        for (int nt = 0; nt < 8; nt++) {
            s[nt][0] = __expf(s[nt][0] - mn0);
            s[nt][1] = __expf(s[nt][1] - mn0);
            s[nt][2] = __expf(s[nt][2] - mn1);
            s[nt][3] = __expf(s[nt][3] - mn1);
            sum0 += s[nt][0] + s[nt][1];
            sum1 += s[nt][2] + s[nt][3];
        }
        sum0 += __shfl_xor_sync(FULL, sum0, 1);
        sum0 += __shfl_xor_sync(FULL, sum0, 2);
        sum1 += __shfl_xor_sync(FULL, sum1, 1);
        sum1 += __shfl_xor_sync(FULL, sum1, 2);
        l0 = l0 * corr0 + sum0;
        l1 = l1 * corr1 + sum1;

#pragma unroll
        for (int nt = 0; nt < 8; nt++) {
            oacc[nt][0] *= corr0; oacc[nt][1] *= corr0;
            oacc[nt][2] *= corr1; oacc[nt][3] *= corr1;
        }

        // ---- O += P V : ksteps over k-rows; A frag built from s via shfl.
#pragma unroll
        for (int kk = 0; kk < 8; kk++) {
            float e, o_;
            e  = __shfl_sync(FULL, s[kk][0], srcA);
            o_ = __shfl_sync(FULL, s[kk][1], srcA);
            float p0 = (t & 1) ? o_ : e;
            e  = __shfl_sync(FULL, s[kk][2], srcA);
            o_ = __shfl_sync(FULL, s[kk][3], srcA);
            float p1 = (t & 1) ? o_ : e;
            e  = __shfl_sync(FULL, s[kk][0], srcB);
            o_ = __shfl_sync(FULL, s[kk][1], srcB);
            float p2 = (t & 1) ? o_ : e;
            e  = __shfl_sync(FULL, s[kk][2], srcB);
            o_ = __shfl_sync(FULL, s[kk][3], srcB);
            float p3 = (t & 1) ? o_ : e;
            unsigned pa[4] = {f2tf32(p0), f2tf32(p1), f2tf32(p2), f2tf32(p3)};
#pragma unroll
            for (int nt = 0; nt < 8; nt++) {
                unsigned b0 = Vs[(kk * 8 + t)     * VSTR + nt * 8 + g];
                unsigned b1 = Vs[(kk * 8 + t + 4) * VSTR + nt * 8 + g];
                mma_tf32(oacc[nt], pa, b0, b1);
            }
        }
    }

    // ---- epilogue: normalize, write ctx[b][s][h*64+d]
    float inv0 = 1.f / l0, inv1 = 1.f / l1;
    int r0 = s0 + wid * 16 + g;
#pragma unroll
    for (int nt = 0; nt < 8; nt++) {
        int col = h * DHEAD + nt * 8 + 2 * t;
        float2 w0 = make_float2(oacc[nt][0] * inv0, oacc[nt][1] * inv0);
        float2 w1 = make_float2(oacc[nt][2] * inv1, oacc[nt][3] * inv1);
        *(float2*)(ctx + (size_t)(b * SEQ + r0) * DMODEL + col)     = w0;
        *(float2*)(ctx + (size_t)(b * SEQ + r0 + 8) * DMODEL + col) = w1;
    }
}

// ---------------------------------------------------------------------------
// Launch
// ---------------------------------------------------------------------------
extern "C" void kernel_launch(void* const* d_in, const int* in_sizes, int n_in,
                              void* d_out, int out_size)
{
    (void)in_sizes; (void)n_in; (void)out_size;
    const float* x      = (const float*)d_in[0];   // [4,2048,1024]
    const int*   p      = (const int*)  d_in[1];   // [4,2048]
    const float* Wqkv_w = (const float*)d_in[2];   // [3072,1024]
    const float* Wqkv_b = (const float*)d_in[3];   // [3072]
    const float* Wo_w   = (const float*)d_in[4];   // [1024,1024]
    const float* Wo_b   = (const float*)d_in[5];   // [1024]
    float* out = (float*)d_out;                    // [4,2048,1024]

    float *qkv, *q, *k, *v, *ctx;
    cudaGetSymbolAddress((void**)&qkv, g_qkv);
    cudaGetSymbolAddress((void**)&q,   g_q);
    cudaGetSymbolAddress((void**)&k,   g_k);
    cudaGetSymbolAddress((void**)&v,   g_v);
    cudaGetSymbolAddress((void**)&ctx, g_ctx);

    // 1) QKV projection (tf32 tensor cores)
    {
        dim3 grid(N_QKV / TBN, MROWS / TBM);
        tf32gemm_nt_bias<<<grid, 256>>>(x, Wqkv_w, Wqkv_b, qkv, MROWS, N_QKV, DMODEL);
    }
    // 2) RoPE + split into [B,H,S,Dh]
    {
        int total = BATCH * NHEAD * SEQ * 32;
        rope_split_kernel<<<(total + 255) / 256, 256>>>(qkv, p, q, k, v);
    }
    // 3) Tensor-core flash attention -> ctx in [B,S,D]
    {
        dim3 grid(SEQ / FTQ, BATCH * NHEAD);
        flash_attn_tc_kernel<<<grid, 256>>>(q, k, v, ctx);
    }
    // 4) Output projection (tf32 tensor cores)
    {
        dim3 grid(DMODEL / TBN, MROWS / TBM);
        tf32gemm_nt_bias<<<grid, 256>>>(ctx, Wo_w, Wo_b, out, MROWS, DMODEL, DMODEL);
    }
}